// round 2
// baseline (speedup 1.0000x reference)
#include <cuda_runtime.h>
#include <math.h>
#include <stdint.h>

#define Zd  128
#define Nd  256
#define Fd  2048
#define Bd  8192
#define OSTRIDE 129   // Z+1

// ---------------- device scratch (no allocations allowed) ----------------
__device__ float g_h1[4][Nd];
__device__ float g_win [Fd * Zd];
__device__ float g_wout[Fd * Zd];
__device__ float g_bias[Fd];
__device__ float g_gate[Fd];
__device__ float g_gs  [Fd];   // gate[f] * s[f]

// ---------------- kernel 1: hypernet h0 -> h1 ----------------
__global__ void k_h1(const float* __restrict__ t,
                     const float* __restrict__ W1, const float* __restrict__ B1,
                     const float* __restrict__ W2, const float* __restrict__ B2) {
    __shared__ float h0[Nd];
    const int k = blockIdx.x;
    const int n = threadIdx.x;
    const float ts = t[0];
    h0[n] = tanhf(fmaf(W1[k * Nd + n], ts, B1[k * Nd + n]));
    __syncthreads();
    const float* __restrict__ w2 = W2 + (size_t)k * Nd * Nd + (size_t)n * Nd;
    float acc = B2[k * Nd + n];
#pragma unroll 8
    for (int m = 0; m < Nd; m++) acc = fmaf(w2[m], h0[m], acc);
    g_h1[k][n] = tanhf(acc);
}

// ---------------- kernel 2: w_in / w_out matvecs (HBM streaming) ----------------
__global__ void k_wproj(const float* __restrict__ W3_win,  const float* __restrict__ b3_win,
                        const float* __restrict__ W3_wout, const float* __restrict__ b3_wout) {
    __shared__ float h1a[Nd], h1b[Nd];
    const int t = threadIdx.x;
    h1a[t] = g_h1[0][t];
    h1b[t] = g_h1[1][t];
    __syncthreads();

    const int wid  = t >> 5;
    const int lane = t & 31;
    long r = (long)blockIdx.x * 8 + wid;

    const float* wmat; const float* bias; const float* hv; float* outp; long rr;
    if (r < (long)Fd * Zd) { rr = r;                 wmat = W3_win;  bias = b3_win;  hv = h1a; outp = g_win;  }
    else                   { rr = r - (long)Fd * Zd; wmat = W3_wout; bias = b3_wout; hv = h1b; outp = g_wout; }

    const float4* __restrict__ row = (const float4*)(wmat + rr * Nd);
    const float4* __restrict__ hv4 = (const float4*)hv;
    float acc = 0.f;
#pragma unroll
    for (int i = 0; i < 2; i++) {
        float4 v = row[lane + i * 32];
        float4 h = hv4[lane + i * 32];
        acc = fmaf(v.x, h.x, acc);
        acc = fmaf(v.y, h.y, acc);
        acc = fmaf(v.z, h.z, acc);
        acc = fmaf(v.w, h.w, acc);
    }
#pragma unroll
    for (int o = 16; o > 0; o >>= 1) acc += __shfl_xor_sync(0xFFFFFFFFu, acc, o);
    if (lane == 0) outp[rr] = acc + bias[rr];
}

// ---------------- kernel 3: bias, gate, gate*s ----------------
__global__ void k_small(const float* __restrict__ W3_b,    const float* __restrict__ b3_b,
                        const float* __restrict__ W3_gate, const float* __restrict__ b3_gate) {
    __shared__ float h2[Nd], h3[Nd];
    const int t = threadIdx.x;
    h2[t] = g_h1[2][t];  h2[t + 128] = g_h1[2][t + 128];
    h3[t] = g_h1[3][t];  h3[t + 128] = g_h1[3][t + 128];
    __syncthreads();

    const int wid  = t >> 5;
    const int lane = t & 31;
    const int f = blockIdx.x * 4 + wid;

    const float4* rb = (const float4*)(W3_b    + (size_t)f * Nd);
    const float4* rg = (const float4*)(W3_gate + (size_t)f * Nd);
    const float4* h2v = (const float4*)h2;
    const float4* h3v = (const float4*)h3;

    float accb = 0.f, accg = 0.f;
#pragma unroll
    for (int i = 0; i < 2; i++) {
        float4 v = rb[lane + i * 32], h = h2v[lane + i * 32];
        accb = fmaf(v.x, h.x, fmaf(v.y, h.y, fmaf(v.z, h.z, fmaf(v.w, h.w, accb))));
        float4 v2 = rg[lane + i * 32], h4 = h3v[lane + i * 32];
        accg = fmaf(v2.x, h4.x, fmaf(v2.y, h4.y, fmaf(v2.z, h4.z, fmaf(v2.w, h4.w, accg))));
    }
    const float4 a  = ((const float4*)(g_win  + (size_t)f * Zd))[lane];
    const float4 b4 = ((const float4*)(g_wout + (size_t)f * Zd))[lane];
    float accs = a.x * b4.x + a.y * b4.y + a.z * b4.z + a.w * b4.w;

#pragma unroll
    for (int o = 16; o > 0; o >>= 1) {
        accb += __shfl_xor_sync(0xFFFFFFFFu, accb, o);
        accg += __shfl_xor_sync(0xFFFFFFFFu, accg, o);
        accs += __shfl_xor_sync(0xFFFFFFFFu, accs, o);
    }
    if (lane == 0) {
        g_bias[f] = accb + b3_b[f];
        float gt = 1.f / (1.f + expf(-(accg + b3_gate[f])));
        g_gate[f] = gt;
        g_gs[f]   = gt * accs;
    }
}

// ---------------- kernel 4: fused double GEMM + trace ----------------
// BM=32 batch rows per block, all Z=128 cols, F looped in BF=64 tiles.
// 256 threads, 2 CTAs/SM (regs<=128, smem ~95KB).
#define BM   32
#define BF   64
#define ZPAD 36   // 32 rows + 4 pad
#define WPAD 68   // 64 f + 4 pad

#define SMEM_FLOATS (Zd*ZPAD /*zs*/ + Zd*WPAD /*ws*/ + BF*Zd /*wo*/ + BM*WPAD /*gsm*/ + BM*17 /*trb*/)
#define SMEM_BYTES  (SMEM_FLOATS * 4)

__global__ __launch_bounds__(256, 2)
void k_main(const float* __restrict__ zlp, float* __restrict__ out) {
    extern __shared__ float sm[];
    float* zs  = sm;                    // [Zd][ZPAD]  zs[k][m]   (z transposed)
    float* ws  = zs  + Zd * ZPAD;       // [Zd][WPAD]  ws[k][fi]  (w_in tile transposed)
    float* wo  = ws  + Zd * WPAD;       // [BF][Zd]    w_out tile natural
    float* gsm = wo  + BF * Zd;         // [BM][WPAD]  g tile
    float* trb = gsm + BM * WPAD;       // [BM][17]

    const int t  = threadIdx.x;
    const int b0 = blockIdx.x * BM;

    // GEMM1 mapping: 16(ty, 2 rows) x 16(tx, 4 f)
    const int tx = t & 15;
    const int ty = t >> 4;
    // GEMM2 mapping: 8(rg, 4 rows) x 32(cg, 4 cols)
    const int cg = t & 31;
    const int rg = t >> 5;

    // load z tile transposed (once)
#pragma unroll
    for (int i = 0; i < (BM * Zd) / 256; i++) {
        int idx = t + i * 256;
        int m = idx >> 7, k = idx & 127;
        zs[k * ZPAD + m] = zlp[(size_t)(b0 + m) * OSTRIDE + k];
    }

    float dz[4][4];
#pragma unroll
    for (int i = 0; i < 4; i++)
#pragma unroll
        for (int j = 0; j < 4; j++) dz[i][j] = 0.f;
    float tracc[2] = {0.f, 0.f};

    for (int f0 = 0; f0 < Fd; f0 += BF) {
        __syncthreads();
        // load w_in tile transposed
#pragma unroll
        for (int i = 0; i < (BF * Zd) / 256; i++) {
            int idx = t + i * 256;
            int fi = idx >> 7, k = idx & 127;
            ws[k * WPAD + fi] = g_win[(size_t)(f0 + fi) * Zd + k];
        }
        // load w_out tile (natural, float4)
        {
            const float4* src = (const float4*)(g_wout + (size_t)f0 * Zd);
            float4* dst = (float4*)wo;
#pragma unroll
            for (int i = 0; i < (BF * Zd / 4) / 256; i++) dst[t + i * 256] = src[t + i * 256];
        }
        __syncthreads();

        // ---- GEMM1: h tile (32x64), microtile 2x4 ----
        float acc[2][4];
#pragma unroll
        for (int i = 0; i < 2; i++)
#pragma unroll
            for (int j = 0; j < 4; j++) acc[i][j] = 0.f;

        const float* zp = zs + ty * 2;
        const float* wp = ws + tx * 4;
#pragma unroll 8
        for (int k = 0; k < Zd; k++) {
            float2 a = *(const float2*)(zp + k * ZPAD);
            float4 b = *(const float4*)(wp + k * WPAD);
            acc[0][0] = fmaf(a.x, b.x, acc[0][0]);
            acc[0][1] = fmaf(a.x, b.y, acc[0][1]);
            acc[0][2] = fmaf(a.x, b.z, acc[0][2]);
            acc[0][3] = fmaf(a.x, b.w, acc[0][3]);
            acc[1][0] = fmaf(a.y, b.x, acc[1][0]);
            acc[1][1] = fmaf(a.y, b.y, acc[1][1]);
            acc[1][2] = fmaf(a.y, b.z, acc[1][2]);
            acc[1][3] = fmaf(a.y, b.w, acc[1][3]);
        }

        // epilogue: tanh, gate, trace, stage g to smem (float4 stores)
        {
            const int fb = f0 + tx * 4;
            float bias[4], gate[4], gs[4];
#pragma unroll
            for (int j = 0; j < 4; j++) {
                bias[j] = g_bias[fb + j];
                gate[j] = g_gate[fb + j];
                gs[j]   = g_gs[fb + j];
            }
#pragma unroll
            for (int i = 0; i < 2; i++) {
                float4 gv;
                float g0, g1, g2, g3;
                {
                    float h = tanhf(acc[i][0] + bias[0]);
                    g0 = h * gate[0];
                    tracc[i] = fmaf(1.f - h * h, gs[0], tracc[i]);
                }
                {
                    float h = tanhf(acc[i][1] + bias[1]);
                    g1 = h * gate[1];
                    tracc[i] = fmaf(1.f - h * h, gs[1], tracc[i]);
                }
                {
                    float h = tanhf(acc[i][2] + bias[2]);
                    g2 = h * gate[2];
                    tracc[i] = fmaf(1.f - h * h, gs[2], tracc[i]);
                }
                {
                    float h = tanhf(acc[i][3] + bias[3]);
                    g3 = h * gate[3];
                    tracc[i] = fmaf(1.f - h * h, gs[3], tracc[i]);
                }
                gv.x = g0; gv.y = g1; gv.z = g2; gv.w = g3;
                *(float4*)(gsm + (ty * 2 + i) * WPAD + tx * 4) = gv;
            }
        }
        __syncthreads();

        // ---- GEMM2: dz += g_tile @ w_out_tile, microtile 4x4 ----
        const float* grow = gsm + (rg * 4) * WPAD;
#pragma unroll 4
        for (int fi = 0; fi < BF; fi++) {
            float4 w4 = *(const float4*)(wo + fi * Zd + cg * 4);
            float gv0 = grow[0 * WPAD + fi];
            float gv1 = grow[1 * WPAD + fi];
            float gv2 = grow[2 * WPAD + fi];
            float gv3 = grow[3 * WPAD + fi];
            dz[0][0] = fmaf(gv0, w4.x, dz[0][0]);
            dz[0][1] = fmaf(gv0, w4.y, dz[0][1]);
            dz[0][2] = fmaf(gv0, w4.z, dz[0][2]);
            dz[0][3] = fmaf(gv0, w4.w, dz[0][3]);
            dz[1][0] = fmaf(gv1, w4.x, dz[1][0]);
            dz[1][1] = fmaf(gv1, w4.y, dz[1][1]);
            dz[1][2] = fmaf(gv1, w4.z, dz[1][2]);
            dz[1][3] = fmaf(gv1, w4.w, dz[1][3]);
            dz[2][0] = fmaf(gv2, w4.x, dz[2][0]);
            dz[2][1] = fmaf(gv2, w4.y, dz[2][1]);
            dz[2][2] = fmaf(gv2, w4.z, dz[2][2]);
            dz[2][3] = fmaf(gv2, w4.w, dz[2][3]);
            dz[3][0] = fmaf(gv3, w4.x, dz[3][0]);
            dz[3][1] = fmaf(gv3, w4.y, dz[3][1]);
            dz[3][2] = fmaf(gv3, w4.z, dz[3][2]);
            dz[3][3] = fmaf(gv3, w4.w, dz[3][3]);
        }
    }

    // write dz_dt
    const float invF = 1.0f / (float)Fd;
#pragma unroll
    for (int rr = 0; rr < 4; rr++) {
        size_t base = (size_t)(b0 + rg * 4 + rr) * OSTRIDE + cg * 4;
        out[base + 0] = dz[rr][0] * invF;
        out[base + 1] = dz[rr][1] * invF;
        out[base + 2] = dz[rr][2] * invF;
        out[base + 3] = dz[rr][3] * invF;
    }

    // trace reduction (over the 16 tx groups)
    __syncthreads();
#pragma unroll
    for (int i = 0; i < 2; i++) trb[(ty * 2 + i) * 17 + tx] = tracc[i];
    __syncthreads();
    if (t < BM) {
        float s = 0.f;
#pragma unroll
        for (int x = 0; x < 16; x++) s += trb[t * 17 + x];
        out[(size_t)(b0 + t) * OSTRIDE + Zd] = -s * invF;
    }
}

// ---------------- launch ----------------
extern "C" void kernel_launch(void* const* d_in, const int* in_sizes, int n_in,
                              void* d_out, int out_size) {
    const float* t       = (const float*)d_in[0];
    const float* zlp     = (const float*)d_in[1];
    const float* W1      = (const float*)d_in[2];
    const float* B1      = (const float*)d_in[3];
    const float* W2      = (const float*)d_in[4];
    const float* B2      = (const float*)d_in[5];
    const float* W3_win  = (const float*)d_in[6];
    const float* b3_win  = (const float*)d_in[7];
    const float* W3_wout = (const float*)d_in[8];
    const float* b3_wout = (const float*)d_in[9];
    const float* W3_b    = (const float*)d_in[10];
    const float* b3_b    = (const float*)d_in[11];
    const float* W3_gate = (const float*)d_in[12];
    const float* b3_gate = (const float*)d_in[13];
    float* out = (float*)d_out;

    cudaFuncSetAttribute(k_main, cudaFuncAttributeMaxDynamicSharedMemorySize, SMEM_BYTES);

    k_h1   <<<4,     256>>>(t, W1, B1, W2, B2);
    k_wproj<<<65536, 256>>>(W3_win, b3_win, W3_wout, b3_wout);
    k_small<<<512,   128>>>(W3_b, b3_b, W3_gate, b3_gate);
    k_main <<<Bd / BM, 256, SMEM_BYTES>>>(zlp, out);
}

// round 4
// speedup vs baseline: 1.7081x; 1.7081x over previous
#include <cuda_runtime.h>
#include <cuda_bf16.h>
#include <math.h>
#include <stdint.h>

#define Zd  128
#define Nd  256
#define Fd  2048
#define Bd  8192
#define OSTRIDE 129   // Z+1

#define TMr 64        // batch rows per CTA
#define BF  64        // f tile
#define NT  (Fd / BF) // 32 tiles

// ---------------- device scratch ----------------
__device__ float g_h1[4][Nd];
__device__ float g_win  [Fd * Zd];
__device__ float g_wout [Fd * Zd];
__device__ float g_woutT[Zd * Fd];   // transposed copy for k_tc staging
__device__ float g_bias[Fd];
__device__ float g_gate[Fd];
__device__ float g_gs  [Fd];         // gate[f] * s[f]

// ---------------- smem word layout for k_tc ----------------
#define STZ 68   // words per row, K=128 bf16 (64 words) + 4 pad
#define STG 36   // words per row, K=64  bf16 (32 words) + 4 pad
#define O_ZHI   0
#define O_ZLO   (O_ZHI   + 64 * STZ)
#define O_WIHI  (O_ZLO   + 64 * STZ)
#define O_WILO  (O_WIHI  + 64 * STZ)
#define O_WOTHI (O_WILO  + 64 * STZ)
#define O_WOTLO (O_WOTHI + 128 * STG)
#define O_GHI   (O_WOTLO + 128 * STG)
#define O_GLO   (O_GHI   + 64 * STG)
#define O_BIAS  (O_GLO   + 64 * STG)
#define O_GATE  (O_BIAS  + 64)
#define O_GS    (O_GATE  + 64)
#define O_TRS   (O_GS    + 64)
#define SMEMW   (O_TRS   + 64 * 4)
#define SMEM_TC (SMEMW * 4)

// split fp32 pair -> packed bf16 hi word + lo word
__device__ __forceinline__ uint32_t pack_split(float a, float b, uint32_t& lopack) {
    __nv_bfloat16 ah = __float2bfloat16_rn(a);
    __nv_bfloat16 bh = __float2bfloat16_rn(b);
    __nv_bfloat16 al = __float2bfloat16_rn(a - __bfloat162float(ah));
    __nv_bfloat16 bl = __float2bfloat16_rn(b - __bfloat162float(bh));
    lopack = (uint32_t)__bfloat16_as_ushort(al) | ((uint32_t)__bfloat16_as_ushort(bl) << 16);
    return (uint32_t)__bfloat16_as_ushort(ah) | ((uint32_t)__bfloat16_as_ushort(bh) << 16);
}

__device__ __forceinline__ void mma_bf16(float* c, const uint32_t* a, const uint32_t* b) {
    asm volatile(
        "mma.sync.aligned.m16n8k16.row.col.f32.bf16.bf16.f32 "
        "{%0,%1,%2,%3}, {%4,%5,%6,%7}, {%8,%9}, {%0,%1,%2,%3};"
        : "+f"(c[0]), "+f"(c[1]), "+f"(c[2]), "+f"(c[3])
        : "r"(a[0]), "r"(a[1]), "r"(a[2]), "r"(a[3]), "r"(b[0]), "r"(b[1]));
}

// ---------------- kernel 1: hypernet h0 -> h1 ----------------
__global__ void k_h1(const float* __restrict__ t,
                     const float* __restrict__ W1, const float* __restrict__ B1,
                     const float* __restrict__ W2, const float* __restrict__ B2) {
    __shared__ float h0[Nd];
    const int k = blockIdx.x;
    const int n = threadIdx.x;
    const float ts = t[0];
    h0[n] = tanhf(fmaf(W1[k * Nd + n], ts, B1[k * Nd + n]));
    __syncthreads();
    const float* __restrict__ w2 = W2 + (size_t)k * Nd * Nd + (size_t)n * Nd;
    float acc = B2[k * Nd + n];
#pragma unroll 8
    for (int m = 0; m < Nd; m++) acc = fmaf(w2[m], h0[m], acc);
    g_h1[k][n] = tanhf(acc);
}

// ---------------- kernel 2: w_in / w_out matvecs (HBM streaming) ----------------
__global__ void k_wproj(const float* __restrict__ W3_win,  const float* __restrict__ b3_win,
                        const float* __restrict__ W3_wout, const float* __restrict__ b3_wout) {
    __shared__ float h1a[Nd], h1b[Nd];
    const int t = threadIdx.x;
    h1a[t] = g_h1[0][t];
    h1b[t] = g_h1[1][t];
    __syncthreads();

    const int wid  = t >> 5;
    const int lane = t & 31;
    long r = (long)blockIdx.x * 8 + wid;

    const float* wmat; const float* bias; const float* hv; long rr; int isOut;
    if (r < (long)Fd * Zd) { rr = r;                 wmat = W3_win;  bias = b3_win;  hv = h1a; isOut = 0; }
    else                   { rr = r - (long)Fd * Zd; wmat = W3_wout; bias = b3_wout; hv = h1b; isOut = 1; }

    const float4* __restrict__ row = (const float4*)(wmat + rr * Nd);
    const float4* __restrict__ hv4 = (const float4*)hv;
    float acc = 0.f;
#pragma unroll
    for (int i = 0; i < 2; i++) {
        float4 v = row[lane + i * 32];
        float4 h = hv4[lane + i * 32];
        acc = fmaf(v.x, h.x, acc);
        acc = fmaf(v.y, h.y, acc);
        acc = fmaf(v.z, h.z, acc);
        acc = fmaf(v.w, h.w, acc);
    }
#pragma unroll
    for (int o = 16; o > 0; o >>= 1) acc += __shfl_xor_sync(0xFFFFFFFFu, acc, o);
    if (lane == 0) {
        float v = acc + bias[rr];
        if (isOut) {
            g_wout[rr] = v;
            int f = (int)(rr >> 7);
            int z = (int)(rr & 127);
            g_woutT[(size_t)z * Fd + f] = v;
        } else {
            g_win[rr] = v;
        }
    }
}

// ---------------- kernel 3: bias, gate, gate*s ----------------
__global__ void k_small(const float* __restrict__ W3_b,    const float* __restrict__ b3_b,
                        const float* __restrict__ W3_gate, const float* __restrict__ b3_gate) {
    __shared__ float h2[Nd], h3[Nd];
    const int t = threadIdx.x;
    h2[t] = g_h1[2][t];  h2[t + 128] = g_h1[2][t + 128];
    h3[t] = g_h1[3][t];  h3[t + 128] = g_h1[3][t + 128];
    __syncthreads();

    const int wid  = t >> 5;
    const int lane = t & 31;
    const int f = blockIdx.x * 4 + wid;

    const float4* rb = (const float4*)(W3_b    + (size_t)f * Nd);
    const float4* rg = (const float4*)(W3_gate + (size_t)f * Nd);
    const float4* h2v = (const float4*)h2;
    const float4* h3v = (const float4*)h3;

    float accb = 0.f, accg = 0.f;
#pragma unroll
    for (int i = 0; i < 2; i++) {
        float4 v = rb[lane + i * 32], h = h2v[lane + i * 32];
        accb = fmaf(v.x, h.x, fmaf(v.y, h.y, fmaf(v.z, h.z, fmaf(v.w, h.w, accb))));
        float4 v2 = rg[lane + i * 32], h4 = h3v[lane + i * 32];
        accg = fmaf(v2.x, h4.x, fmaf(v2.y, h4.y, fmaf(v2.z, h4.z, fmaf(v2.w, h4.w, accg))));
    }
    const float4 a  = ((const float4*)(g_win  + (size_t)f * Zd))[lane];
    const float4 b4 = ((const float4*)(g_wout + (size_t)f * Zd))[lane];
    float accs = a.x * b4.x + a.y * b4.y + a.z * b4.z + a.w * b4.w;

#pragma unroll
    for (int o = 16; o > 0; o >>= 1) {
        accb += __shfl_xor_sync(0xFFFFFFFFu, accb, o);
        accg += __shfl_xor_sync(0xFFFFFFFFu, accg, o);
        accs += __shfl_xor_sync(0xFFFFFFFFu, accs, o);
    }
    if (lane == 0) {
        g_bias[f] = accb + b3_b[f];
        float gt = 1.f / (1.f + expf(-(accg + b3_gate[f])));
        g_gate[f] = gt;
        g_gs[f]   = gt * accs;
    }
}

// ---------------- kernel 4: bf16x3 mma.sync fused double GEMM ----------------
__global__ __launch_bounds__(256, 1)
void k_tc(const float* __restrict__ zlp, float* __restrict__ out) {
    extern __shared__ uint32_t smw[];
    float* smf = (float*)smw;

    const int t    = threadIdx.x;
    const int lane = t & 31;
    const int wid  = t >> 5;
    const int g    = lane >> 2;      // group 0..7
    const int tq   = lane & 3;       // thread-in-group 0..3
    const int wr   = wid >> 2;       // 0..1 (m)
    const int wc   = wid & 3;        // 0..3 (f for GEMM1, z for GEMM2)
    const int b0   = blockIdx.x * TMr;

    // ---- stage z (hi/lo bf16), 64 rows x 64 words ----
#pragma unroll
    for (int it = 0; it < 16; it++) {
        int idx = t + it * 256;
        int m = idx >> 6, kp = idx & 63;
        const float* zr = zlp + (size_t)(b0 + m) * OSTRIDE + 2 * kp;
        uint32_t lo, hi = pack_split(zr[0], zr[1], lo);
        smw[O_ZHI + m * STZ + kp] = hi;
        smw[O_ZLO + m * STZ + kp] = lo;
    }

    float dz[2][4][4];
#pragma unroll
    for (int i = 0; i < 2; i++)
#pragma unroll
        for (int j = 0; j < 4; j++)
#pragma unroll
            for (int q = 0; q < 4; q++) dz[i][j][q] = 0.f;
    float tracc[4] = {0.f, 0.f, 0.f, 0.f};

    for (int tile = 0; tile < NT; tile++) {
        const int f0 = tile * BF;
        __syncthreads();   // prev GEMM2 done with wi/wot buffers

        // stage w_in tile [64 f][128 k]
#pragma unroll
        for (int it = 0; it < 16; it++) {
            int idx = t + it * 256;
            int fi = idx >> 6, kp = idx & 63;
            const float* src = g_win + (size_t)(f0 + fi) * Zd + 2 * kp;
            uint32_t lo, hi = pack_split(src[0], src[1], lo);
            smw[O_WIHI + fi * STZ + kp] = hi;
            smw[O_WILO + fi * STZ + kp] = lo;
        }
        // stage woT tile [128 z][64 f] from g_woutT (coalesced read, conflict-free write)
#pragma unroll
        for (int it = 0; it < 16; it++) {
            int idx = t + it * 256;
            int fp = idx & 31, z = idx >> 5;
            const float* src = g_woutT + (size_t)z * Fd + f0 + 2 * fp;
            uint32_t lo, hi = pack_split(src[0], src[1], lo);
            smw[O_WOTHI + z * STG + fp] = hi;
            smw[O_WOTLO + z * STG + fp] = lo;
        }
        if (t < BF) {
            smf[O_BIAS + t] = g_bias[f0 + t];
            smf[O_GATE + t] = g_gate[f0 + t];
            smf[O_GS   + t] = g_gs[f0 + t];
        }
        __syncthreads();

        // ---- GEMM1: c1 = z @ w_in^T  (64x64, warp 32x16) ----
        float c1[2][2][4];
#pragma unroll
        for (int i = 0; i < 2; i++)
#pragma unroll
            for (int j = 0; j < 2; j++)
#pragma unroll
                for (int q = 0; q < 4; q++) c1[i][j][q] = 0.f;

#pragma unroll
        for (int kk = 0; kk < 8; kk++) {
            const int kw = kk * 8 + tq;
            uint32_t ah[2][4], al[2][4], bh[2][2], bl[2][2];
#pragma unroll
            for (int i = 0; i < 2; i++) {
                int base = (wr * 32 + i * 16 + g) * STZ + kw;
                ah[i][0] = smw[O_ZHI + base];
                ah[i][1] = smw[O_ZHI + base + 8 * STZ];
                ah[i][2] = smw[O_ZHI + base + 4];
                ah[i][3] = smw[O_ZHI + base + 8 * STZ + 4];
                al[i][0] = smw[O_ZLO + base];
                al[i][1] = smw[O_ZLO + base + 8 * STZ];
                al[i][2] = smw[O_ZLO + base + 4];
                al[i][3] = smw[O_ZLO + base + 8 * STZ + 4];
            }
#pragma unroll
            for (int j = 0; j < 2; j++) {
                int base = (wc * 16 + j * 8 + g) * STZ + kw;
                bh[j][0] = smw[O_WIHI + base];
                bh[j][1] = smw[O_WIHI + base + 4];
                bl[j][0] = smw[O_WILO + base];
                bl[j][1] = smw[O_WILO + base + 4];
            }
#pragma unroll
            for (int i = 0; i < 2; i++)
#pragma unroll
                for (int j = 0; j < 2; j++) {
                    mma_bf16(c1[i][j], ah[i], bh[j]);
                    mma_bf16(c1[i][j], al[i], bh[j]);
                    mma_bf16(c1[i][j], ah[i], bl[j]);
                }
        }

        // ---- epilogue: tanh/gate/trace, stage g (hi/lo bf16) ----
#pragma unroll
        for (int i = 0; i < 2; i++)
#pragma unroll
            for (int j = 0; j < 2; j++) {
                const int fc = wc * 16 + j * 8 + 2 * tq;
                const float bi0 = smf[O_BIAS + fc], bi1 = smf[O_BIAS + fc + 1];
                const float ga0 = smf[O_GATE + fc], ga1 = smf[O_GATE + fc + 1];
                const float gs0 = smf[O_GS + fc],   gs1 = smf[O_GS + fc + 1];
                const int r  = wr * 32 + i * 16 + g;
                const int cw = wc * 8 + j * 4 + tq;
                {
                    float h0 = tanhf(c1[i][j][0] + bi0);
                    float h1 = tanhf(c1[i][j][1] + bi1);
                    tracc[i * 2 + 0] += (1.f - h0 * h0) * gs0 + (1.f - h1 * h1) * gs1;
                    uint32_t lo, hi = pack_split(h0 * ga0, h1 * ga1, lo);
                    smw[O_GHI + r * STG + cw] = hi;
                    smw[O_GLO + r * STG + cw] = lo;
                }
                {
                    float h2 = tanhf(c1[i][j][2] + bi0);
                    float h3 = tanhf(c1[i][j][3] + bi1);
                    tracc[i * 2 + 1] += (1.f - h2 * h2) * gs0 + (1.f - h3 * h3) * gs1;
                    uint32_t lo, hi = pack_split(h2 * ga0, h3 * ga1, lo);
                    smw[O_GHI + (r + 8) * STG + cw] = hi;
                    smw[O_GLO + (r + 8) * STG + cw] = lo;
                }
            }
        __syncthreads();

        // ---- GEMM2: dz += g @ w_out_tile (warp 32m x 32z, k=64) ----
#pragma unroll
        for (int kk = 0; kk < 4; kk++) {
            const int kw = kk * 8 + tq;
            uint32_t ah[2][4], al[2][4], bh[4][2], bl[4][2];
#pragma unroll
            for (int i = 0; i < 2; i++) {
                int base = (wr * 32 + i * 16 + g) * STG + kw;
                ah[i][0] = smw[O_GHI + base];
                ah[i][1] = smw[O_GHI + base + 8 * STG];
                ah[i][2] = smw[O_GHI + base + 4];
                ah[i][3] = smw[O_GHI + base + 8 * STG + 4];
                al[i][0] = smw[O_GLO + base];
                al[i][1] = smw[O_GLO + base + 8 * STG];
                al[i][2] = smw[O_GLO + base + 4];
                al[i][3] = smw[O_GLO + base + 8 * STG + 4];
            }
#pragma unroll
            for (int jn = 0; jn < 4; jn++) {
                int base = (wc * 32 + jn * 8 + g) * STG + kw;
                bh[jn][0] = smw[O_WOTHI + base];
                bh[jn][1] = smw[O_WOTHI + base + 4];
                bl[jn][0] = smw[O_WOTLO + base];
                bl[jn][1] = smw[O_WOTLO + base + 4];
            }
#pragma unroll
            for (int i = 0; i < 2; i++)
#pragma unroll
                for (int jn = 0; jn < 4; jn++) {
                    mma_bf16(dz[i][jn], ah[i], bh[jn]);
                    mma_bf16(dz[i][jn], al[i], bh[jn]);
                    mma_bf16(dz[i][jn], ah[i], bl[jn]);
                }
        }
    }

    // ---- write dz ----
    const float invF = 1.0f / (float)Fd;
#pragma unroll
    for (int i = 0; i < 2; i++)
#pragma unroll
        for (int jn = 0; jn < 4; jn++) {
            const int r  = b0 + wr * 32 + i * 16 + g;
            const int z0 = wc * 32 + jn * 8 + 2 * tq;
            out[(size_t)r * OSTRIDE + z0]           = dz[i][jn][0] * invF;
            out[(size_t)r * OSTRIDE + z0 + 1]       = dz[i][jn][1] * invF;
            out[(size_t)(r + 8) * OSTRIDE + z0]     = dz[i][jn][2] * invF;
            out[(size_t)(r + 8) * OSTRIDE + z0 + 1] = dz[i][jn][3] * invF;
        }

    // ---- trace reduction ----
#pragma unroll
    for (int q = 0; q < 4; q++) {
        tracc[q] += __shfl_xor_sync(0xFFFFFFFFu, tracc[q], 1);
        tracc[q] += __shfl_xor_sync(0xFFFFFFFFu, tracc[q], 2);
    }
    if (tq == 0) {
#pragma unroll
        for (int i = 0; i < 2; i++)
#pragma unroll
            for (int hf = 0; hf < 2; hf++) {
                int rl = wr * 32 + i * 16 + hf * 8 + g;
                smf[O_TRS + rl * 4 + wc] = tracc[i * 2 + hf];
            }
    }
    __syncthreads();
    if (t < TMr) {
        float s = smf[O_TRS + t * 4 + 0] + smf[O_TRS + t * 4 + 1] +
                  smf[O_TRS + t * 4 + 2] + smf[O_TRS + t * 4 + 3];
        out[(size_t)(b0 + t) * OSTRIDE + Zd] = -s * invF;
    }
}

// ---------------- launch ----------------
extern "C" void kernel_launch(void* const* d_in, const int* in_sizes, int n_in,
                              void* d_out, int out_size) {
    const float* t       = (const float*)d_in[0];
    const float* zlp     = (const float*)d_in[1];
    const float* W1      = (const float*)d_in[2];
    const float* B1      = (const float*)d_in[3];
    const float* W2      = (const float*)d_in[4];
    const float* B2      = (const float*)d_in[5];
    const float* W3_win  = (const float*)d_in[6];
    const float* b3_win  = (const float*)d_in[7];
    const float* W3_wout = (const float*)d_in[8];
    const float* b3_wout = (const float*)d_in[9];
    const float* W3_b    = (const float*)d_in[10];
    const float* b3_b    = (const float*)d_in[11];
    const float* W3_gate = (const float*)d_in[12];
    const float* b3_gate = (const float*)d_in[13];
    float* out = (float*)d_out;

    cudaFuncSetAttribute(k_tc, cudaFuncAttributeMaxDynamicSharedMemorySize, SMEM_TC);

    k_h1   <<<4,     256>>>(t, W1, B1, W2, B2);
    k_wproj<<<65536, 256>>>(W3_win, b3_win, W3_wout, b3_wout);
    k_small<<<512,   128>>>(W3_b, b3_b, W3_gate, b3_gate);
    k_tc   <<<Bd / TMr, 256, SMEM_TC>>>(zlp, out);
}